// round 7
// baseline (speedup 1.0000x reference)
#include <cuda_runtime.h>
#include <math.h>

#define BB 2
#define NN 160
#define HH 256
#define C3 768
#define FF 512
#define NP (NN*NN)            // 25600
#define MM (BB*NN)            // 320
#define LOGIT_ELEMS (BB*NP*2) // 102400 per head
#define EMB_OFF (3*LOGIT_ELEMS)

// PQ scratch, split-K2: [h = (t*2+s)*2+ks][m][f]
__device__ float g_PQ[3 * 2 * 2 * MM * FF];

#define FFMA2(acc, a, b) asm("fma.rn.f32x2 %0, %1, %2, %0;" : "+l"(acc) : "l"(a), "l"(b))
#define PACKDUP(d, x)    asm("mov.b64 %0, {%1, %1};" : "=l"(d) : "r"(__float_as_uint(x)))
#define UNPK(lo, hi, v)  asm("mov.b64 {%0, %1}, %2;" : "=r"(lo), "=r"(hi) : "l"(v))

// 256-bit global memory ops (sm_100+)
__device__ __forceinline__ void ldg256(const float* p, float4& a, float4& b) {
    asm("ld.global.nc.v8.f32 {%0,%1,%2,%3,%4,%5,%6,%7}, [%8];"
        : "=f"(a.x), "=f"(a.y), "=f"(a.z), "=f"(a.w),
          "=f"(b.x), "=f"(b.y), "=f"(b.z), "=f"(b.w)
        : "l"(p));
}
__device__ __forceinline__ void stg256(float* p, const float4& a, const float4& b) {
    asm volatile("st.global.cs.v8.f32 [%0], {%1,%2,%3,%4,%5,%6,%7,%8};"
        :: "l"(p), "f"(a.x), "f"(a.y), "f"(a.z), "f"(a.w),
           "f"(b.x), "f"(b.y), "f"(b.z), "f"(b.w)
        : "memory");
}

#define BM 64
#define BN 64
#define BK 16
#define NKS 24
#define AST 68
#define GEMM_BLOCKS 480
#define WRA_BLOCKS 1250     // k1 writer tiles
#define LG_BLOCKS 150
#define WRB_BLOCKS 1950     // k2 writer tiles
#define WR_SPLIT WRA_BLOCKS

// writer: 4i x 4j = 16 pairs per 256-thread block, 256-bit ops, MLP=4 batches
// per pair: 1536 floats = 192 chunks of 8 floats (32B). 16*192 = 3072 = 12*256.
__device__ __forceinline__ void writer_role(
    int wb,
    const float* __restrict__ geo, const float* __restrict__ app, const float* __restrict__ con,
    float* __restrict__ out, int tid)
{
    const int b = wb / 1600;
    const int r = wb % 1600;
    const int i0 = (r / 40) * 4;
    const int j0 = (r % 40) * 4;
    const size_t brow = (size_t)b * NN * HH;
    float* outp = out + EMB_OFF;
    const size_t pb0 = (size_t)b * NP;

    #pragma unroll
    for (int base = 0; base < 12; base += 4) {
        float4 va[4], vb[4];
        int pl[4], ul[4];
        #pragma unroll
        for (int w = 0; w < 4; w++) {
            const int lin = tid + (base + w) * 256;   // 0..3071
            const int p = lin / 192;
            const int u = lin - p * 192;
            pl[w] = p; ul[w] = u;
            const int pi = p >> 2, pj = p & 3;
            const bool js = (u < 96);
            const int n = js ? (j0 + pj) : (i0 + pi);
            const int c8 = js ? u : (u - 96);         // 8-float chunk within 768
            const int seg = c8 >> 5;
            const float* bp = (seg == 0) ? geo : ((seg == 1) ? app : con);
            ldg256(bp + brow + (size_t)n * HH + ((c8 & 31) << 3), va[w], vb[w]);
        }
        #pragma unroll
        for (int w = 0; w < 4; w++) {
            const int pi = pl[w] >> 2, pj = pl[w] & 3;
            const size_t pidx = pb0 + (size_t)(i0 + pi) * NN + (j0 + pj);
            stg256(outp + pidx * 1536 + ((size_t)ul[w] << 3), va[w], vb[w]);
        }
    }
}

// ---------------- Kernel 1: split-K2 GEMM + writer half A ----------------
__global__ __launch_bounds__(256, 5) void k1_gemm_wr(
    const float* __restrict__ geo, const float* __restrict__ app, const float* __restrict__ con,
    const float* __restrict__ W1c, const float* __restrict__ b1c,
    const float* __restrict__ W1r, const float* __restrict__ b1r,
    const float* __restrict__ W1l, const float* __restrict__ b1l,
    float* __restrict__ out)
{
    __shared__ float As[2][BK*AST];
    __shared__ float Bs[2][BK*BN];
    const int g = blockIdx.x;
    const int tid = threadIdx.x;

    if (g < GEMM_BLOCKS) {
        const int nt = g % 48;
        const int r  = g / 48;
        const int mt = r >> 1;
        const int ks = r & 1;
        const int t  = nt >> 4;
        const int s  = (nt >> 3) & 1;
        const int f0 = (nt & 7) * BN;
        const float* W1 = (t==0 ? W1c : (t==1 ? W1r : W1l)) + (size_t)s * C3 * FF;
        const float* b1 = (t==0 ? b1c : (t==1 ? b1r : b1l));
        const int m0 = mt * BM;
        const int kbase = ks * 384;

        const int arow = tid >> 2, av = tid & 3;
        const int kr = tid >> 4, fo = (tid & 15) * 4;
        const int rg = tid >> 4, cg = tid & 15;

        unsigned long long acc2[4][2];
        #pragma unroll
        for (int a = 0; a < 4; a++) { acc2[a][0] = 0ull; acc2[a][1] = 0ull; }

        float4 pa, pb;
        {
            const int c0 = kbase;
            const float* segp = (c0 < 256) ? geo : ((c0 < 512) ? app : con);
            pa = *(const float4*)(segp + (size_t)(m0 + arow) * HH + (c0 & 255) + av * 4);
            pb = *(const float4*)(W1 + (size_t)(c0 + kr) * FF + f0 + fo);
        }
        As[0][(av*4+0)*AST + arow] = pa.x;
        As[0][(av*4+1)*AST + arow] = pa.y;
        As[0][(av*4+2)*AST + arow] = pa.z;
        As[0][(av*4+3)*AST + arow] = pa.w;
        *(float4*)&Bs[0][kr*BN + fo] = pb;
        __syncthreads();

        for (int kt = 0; kt < NKS; kt++) {
            const int cur = kt & 1;
            const int nxt = cur ^ 1;
            if (kt + 1 < NKS) {
                const int c0 = kbase + (kt + 1) * BK;
                const float* segp = (c0 < 256) ? geo : ((c0 < 512) ? app : con);
                pa = *(const float4*)(segp + (size_t)(m0 + arow) * HH + (c0 & 255) + av * 4);
                pb = *(const float4*)(W1 + (size_t)(c0 + kr) * FF + f0 + fo);
            }
            #pragma unroll
            for (int k = 0; k < BK; k++) {
                const float4 a4 = *(const float4*)&As[cur][k*AST + rg*4];
                const ulonglong2 b2v = *(const ulonglong2*)&Bs[cur][k*BN + cg*4];
                float avv[4] = {a4.x, a4.y, a4.z, a4.w};
                #pragma unroll
                for (int a = 0; a < 4; a++) {
                    unsigned long long ad;
                    PACKDUP(ad, avv[a]);
                    FFMA2(acc2[a][0], ad, b2v.x);
                    FFMA2(acc2[a][1], ad, b2v.y);
                }
            }
            if (kt + 1 < NKS) {
                __syncthreads();
                As[nxt][(av*4+0)*AST + arow] = pa.x;
                As[nxt][(av*4+1)*AST + arow] = pa.y;
                As[nxt][(av*4+2)*AST + arow] = pa.z;
                As[nxt][(av*4+3)*AST + arow] = pa.w;
                *(float4*)&Bs[nxt][kr*BN + fo] = pb;
                __syncthreads();
            }
        }

        const bool addb = (s == 1) && (ks == 0);
        float bv[4] = {0.f, 0.f, 0.f, 0.f};
        if (addb) {
            const float4 tb = *(const float4*)(b1 + f0 + cg*4);
            bv[0]=tb.x; bv[1]=tb.y; bv[2]=tb.z; bv[3]=tb.w;
        }
        const size_t hb = ((size_t)((t*2 + s) * 2 + ks)) * MM * FF;
        #pragma unroll
        for (int a = 0; a < 4; a++) {
            const int m = m0 + rg*4 + a;
            unsigned int lo0, hi0, lo1, hi1;
            UNPK(lo0, hi0, acc2[a][0]);
            UNPK(lo1, hi1, acc2[a][1]);
            *(float4*)(g_PQ + hb + (size_t)m * FF + f0 + cg*4) =
                make_float4(__uint_as_float(lo0) + bv[0], __uint_as_float(hi0) + bv[1],
                            __uint_as_float(lo1) + bv[2], __uint_as_float(hi1) + bv[3]);
        }
    } else {
        writer_role(g - GEMM_BLOCKS, geo, app, con, out, tid);
    }
}

// ---------------- Kernel 2: logits (32i x 32j, acc[4]) + writer half B ----------------
__global__ __launch_bounds__(256, 6) void k2_lg_wr(
    const float* __restrict__ geo, const float* __restrict__ app, const float* __restrict__ con,
    float* __restrict__ out,
    const float* __restrict__ W2c, const float* __restrict__ b2c,
    const float* __restrict__ W2r, const float* __restrict__ b2r,
    const float* __restrict__ W2l, const float* __restrict__ b2l)
{
    __shared__ float sP[32 * 132];
    __shared__ float sQ[32 * 128];
    __shared__ float sW[128];
    const int g = blockIdx.x;
    const int tid = threadIdx.x;

    if (g < LG_BLOCKS) {
        const int t = g / 50;
        const int r50 = g % 50;
        const int b = r50 / 25;
        const int r25 = r50 % 25;
        const int i0 = (r25 / 5) * 32;
        const int j0 = (r25 % 5) * 32;
        const float* W2 = (t==0 ? W2c : (t==1 ? W2r : W2l));
        const float* b2 = (t==0 ? b2c : (t==1 ? b2r : b2l));
        const size_t boff = (size_t)b * NN * FF;
        const float* P0 = g_PQ + ((size_t)((t*2+0)*2+0)) * MM * FF + boff;
        const float* P1 = g_PQ + ((size_t)((t*2+0)*2+1)) * MM * FF + boff;
        const float* Q0 = g_PQ + ((size_t)((t*2+1)*2+0)) * MM * FF + boff;
        const float* Q1 = g_PQ + ((size_t)((t*2+1)*2+1)) * MM * FF + boff;
        const int il = tid >> 5, jl = tid & 31;
        const int lr = tid >> 3, lv = tid & 7;

        float acc[4] = {0.f, 0.f, 0.f, 0.f};
        for (int fc = 0; fc < 4; fc++) {
            const int f0 = fc * 128;
            {
                const size_t ro = (size_t)(j0 + lr) * FF + f0;
                float* dp = sP + lr * 132;
                #pragma unroll
                for (int u = 0; u < 4; u++) {
                    const int fl = (lv + u * 8) * 4;
                    const float4 x = *(const float4*)(P0 + ro + fl);
                    const float4 y = *(const float4*)(P1 + ro + fl);
                    *(float4*)(dp + fl) = make_float4(x.x+y.x, x.y+y.y, x.z+y.z, x.w+y.w);
                }
            }
            {
                const size_t ro = (size_t)(i0 + lr) * FF + f0;
                float* dp = sQ + lr * 128;
                #pragma unroll
                for (int u = 0; u < 4; u++) {
                    const int fl = (lv + u * 8) * 4;
                    const float4 x = *(const float4*)(Q0 + ro + fl);
                    const float4 y = *(const float4*)(Q1 + ro + fl);
                    *(float4*)(dp + fl) = make_float4(x.x+y.x, x.y+y.y, x.z+y.z, x.w+y.w);
                }
            }
            if (tid < 128) {
                const float2 w2v = ((const float2*)W2)[f0 + tid];
                sW[tid] = w2v.x - w2v.y;
            }
            __syncthreads();

            const float* pr = sP + jl * 132;
            const float* q0 = sQ + (il * 4) * 128;
            #pragma unroll 4
            for (int f = 0; f < 128; f += 4) {
                const float4 p = *(const float4*)(pr + f);
                const float4 w = *(const float4*)(sW + f);
                #pragma unroll
                for (int a = 0; a < 4; a++) {
                    const float4 q = *(const float4*)(q0 + a * 128 + f);
                    acc[a] = fmaf(fmaxf(p.x + q.x, 0.f), w.x, acc[a]);
                    acc[a] = fmaf(fmaxf(p.y + q.y, 0.f), w.y, acc[a]);
                    acc[a] = fmaf(fmaxf(p.z + q.z, 0.f), w.z, acc[a]);
                    acc[a] = fmaf(fmaxf(p.w + q.w, 0.f), w.w, acc[a]);
                }
            }
            __syncthreads();
        }

        const float bd = b2[0] - b2[1];
        float2* o = (float2*)(out + (size_t)t * LOGIT_ELEMS) + (size_t)b * NP;
        const int j = j0 + jl;
        #pragma unroll
        for (int a = 0; a < 4; a++) {
            const float d = acc[a] + bd;
            const float p0 = 1.0f / (1.0f + __expf(-d));
            o[(size_t)(i0 + il*4 + a) * NN + j] = make_float2(p0, 1.0f - p0);
        }
    } else {
        writer_role(WR_SPLIT + (g - LG_BLOCKS), geo, app, con, out, tid);
    }
}

extern "C" void kernel_launch(void* const* d_in, const int* in_sizes, int n_in,
                              void* d_out, int out_size) {
    const float* geo = (const float*)d_in[0];
    const float* app = (const float*)d_in[1];
    const float* con = (const float*)d_in[2];
    const float* W1c = (const float*)d_in[3];
    const float* b1c = (const float*)d_in[4];
    const float* W2c = (const float*)d_in[5];
    const float* b2c = (const float*)d_in[6];
    const float* W1r = (const float*)d_in[7];
    const float* b1r = (const float*)d_in[8];
    const float* W2r = (const float*)d_in[9];
    const float* b2r = (const float*)d_in[10];
    const float* W1l = (const float*)d_in[11];
    const float* b1l = (const float*)d_in[12];
    const float* W2l = (const float*)d_in[13];
    const float* b2l = (const float*)d_in[14];
    float* out = (float*)d_out;

    k1_gemm_wr<<<GEMM_BLOCKS + WRA_BLOCKS, 256>>>(geo, app, con,
                                                  W1c, b1c, W1r, b1r, W1l, b1l, out);
    k2_lg_wr<<<LG_BLOCKS + WRB_BLOCKS, 256>>>(geo, app, con, out,
                                              W2c, b2c, W2r, b2r, W2l, b2l);
}

// round 8
// speedup vs baseline: 1.1745x; 1.1745x over previous
#include <cuda_runtime.h>
#include <math.h>

#define BB 2
#define NN 160
#define HH 256
#define C3 768
#define FF 512
#define NP (NN*NN)            // 25600
#define MM (BB*NN)            // 320
#define LOGIT_ELEMS (BB*NP*2) // 102400 per head
#define EMB_OFF (3*LOGIT_ELEMS)

// PQ scratch: [h = t*2+s][m][f]
// s=0: P (emb[j] @ W1[0:768]); s=1: Q (emb[i] @ W1[768:1536], +b1)
__device__ float g_PQ[3 * 2 * MM * FF];

#define FFMA2(acc, a, b) asm("fma.rn.f32x2 %0, %1, %2, %0;" : "+l"(acc) : "l"(a), "l"(b))
#define PACKDUP(d, x)    asm("mov.b64 %0, {%1, %1};" : "=l"(d) : "r"(__float_as_uint(x)))
#define UNPK(lo, hi, v)  asm("mov.b64 {%0, %1}, %2;" : "=r"(lo), "=r"(hi) : "l"(v))

#define BM 64
#define BN 64
#define BK 16
#define NK 48               // full K = 768
#define AST 68
#define GEMM_BLOCKS 240     // 5 mt * (3 heads * 2 halves * 8 f-chunks)
#define WRA_BLOCKS 1700     // k1 writer tiles
#define LG_BLOCKS 150
#define WRB_BLOCKS 1500     // k2 writer tiles
#define WR_SPLIT WRA_BLOCKS

// writer: 16 pairs (same i) per 256-thread block, batched LDG (MLP=6)
// wb in [0,3200): b = wb/1600, i = (wb%1600)/10, j0 = (wb%10)*16
__device__ __forceinline__ void writer_role(
    int wb,
    const float* __restrict__ geo, const float* __restrict__ app, const float* __restrict__ con,
    float* __restrict__ out, int tid)
{
    const int b = wb / 1600;
    const int rem = wb % 1600;
    const int i = rem / 10;
    const int j0 = (rem % 10) * 16;
    const size_t brow = (size_t)b * NN * HH;
    float4* dst0 = (float4*)(out + EMB_OFF) + (size_t)(b*NP + i*NN + j0) * 384;

    #pragma unroll
    for (int base = 0; base < 24; base += 6) {
        float4 vals[6];
        #pragma unroll
        for (int w = 0; w < 6; w++) {
            const int lin = tid + (base + w) * 256;   // 0..6143
            const int jj = lin / 384;
            const int u  = lin - jj * 384;
            const bool jside = (u < 192);
            const int n = jside ? (j0 + jj) : i;
            const int c = (jside ? u : (u - 192)) * 4;
            const float* bp = (c < 256) ? geo : ((c < 512) ? app : con);
            vals[w] = *(const float4*)(bp + brow + (size_t)n * HH + (c & 255));
        }
        #pragma unroll
        for (int w = 0; w < 6; w++)
            __stcs(dst0 + (base + w) * 256 + tid, vals[w]);
    }
}

// ---------------- Kernel 1: full-K GEMM + writer half A ----------------
__global__ __launch_bounds__(256) void k1_gemm_wr(
    const float* __restrict__ geo, const float* __restrict__ app, const float* __restrict__ con,
    const float* __restrict__ W1c, const float* __restrict__ b1c,
    const float* __restrict__ W1r, const float* __restrict__ b1r,
    const float* __restrict__ W1l, const float* __restrict__ b1l,
    float* __restrict__ out)
{
    __shared__ float As[2][BK*AST];
    __shared__ float Bs[2][BK*BN];
    const int g = blockIdx.x;
    const int tid = threadIdx.x;

    if (g < GEMM_BLOCKS) {
        const int nt = g % 48;
        const int mt = g / 48;
        const int t  = nt >> 4;
        const int s  = (nt >> 3) & 1;
        const int f0 = (nt & 7) * BN;
        const float* W1 = (t==0 ? W1c : (t==1 ? W1r : W1l)) + (size_t)s * C3 * FF;
        const float* b1 = (t==0 ? b1c : (t==1 ? b1r : b1l));
        const int m0 = mt * BM;

        const int arow = tid >> 2, av = tid & 3;
        const int kr = tid >> 4, fo = (tid & 15) * 4;
        const int rg = tid >> 4, cg = tid & 15;

        unsigned long long acc2[4][2];
        #pragma unroll
        for (int a = 0; a < 4; a++) { acc2[a][0] = 0ull; acc2[a][1] = 0ull; }

        float4 pa, pb;
        {
            pa = *(const float4*)(geo + (size_t)(m0 + arow) * HH + av * 4);
            pb = *(const float4*)(W1 + (size_t)kr * FF + f0 + fo);
        }
        As[0][(av*4+0)*AST + arow] = pa.x;
        As[0][(av*4+1)*AST + arow] = pa.y;
        As[0][(av*4+2)*AST + arow] = pa.z;
        As[0][(av*4+3)*AST + arow] = pa.w;
        *(float4*)&Bs[0][kr*BN + fo] = pb;
        __syncthreads();

        for (int kt = 0; kt < NK; kt++) {
            const int cur = kt & 1;
            const int nxt = cur ^ 1;
            if (kt + 1 < NK) {
                const int c0 = (kt + 1) * BK;
                const float* segp = (c0 < 256) ? geo : ((c0 < 512) ? app : con);
                pa = *(const float4*)(segp + (size_t)(m0 + arow) * HH + (c0 & 255) + av * 4);
                pb = *(const float4*)(W1 + (size_t)(c0 + kr) * FF + f0 + fo);
            }
            #pragma unroll
            for (int k = 0; k < BK; k++) {
                const float4 a4 = *(const float4*)&As[cur][k*AST + rg*4];
                const ulonglong2 b2v = *(const ulonglong2*)&Bs[cur][k*BN + cg*4];
                float avv[4] = {a4.x, a4.y, a4.z, a4.w};
                #pragma unroll
                for (int a = 0; a < 4; a++) {
                    unsigned long long ad;
                    PACKDUP(ad, avv[a]);
                    FFMA2(acc2[a][0], ad, b2v.x);
                    FFMA2(acc2[a][1], ad, b2v.y);
                }
            }
            if (kt + 1 < NK) {
                __syncthreads();
                As[nxt][(av*4+0)*AST + arow] = pa.x;
                As[nxt][(av*4+1)*AST + arow] = pa.y;
                As[nxt][(av*4+2)*AST + arow] = pa.z;
                As[nxt][(av*4+3)*AST + arow] = pa.w;
                *(float4*)&Bs[nxt][kr*BN + fo] = pb;
                __syncthreads();
            }
        }

        const bool addb = (s == 1);
        float bv[4] = {0.f, 0.f, 0.f, 0.f};
        if (addb) {
            const float4 tb = *(const float4*)(b1 + f0 + cg*4);
            bv[0]=tb.x; bv[1]=tb.y; bv[2]=tb.z; bv[3]=tb.w;
        }
        const size_t hb = (size_t)(t*2 + s) * MM * FF;
        #pragma unroll
        for (int a = 0; a < 4; a++) {
            const int m = m0 + rg*4 + a;
            unsigned int lo0, hi0, lo1, hi1;
            UNPK(lo0, hi0, acc2[a][0]);
            UNPK(lo1, hi1, acc2[a][1]);
            *(float4*)(g_PQ + hb + (size_t)m * FF + f0 + cg*4) =
                make_float4(__uint_as_float(lo0) + bv[0], __uint_as_float(hi0) + bv[1],
                            __uint_as_float(lo1) + bv[2], __uint_as_float(hi1) + bv[3]);
        }
    } else {
        writer_role(g - GEMM_BLOCKS, geo, app, con, out, tid);
    }
}

// ---------------- Kernel 2: logits (32i x 32j, acc[4]) + writer half B ----------------
__global__ __launch_bounds__(256) void k2_lg_wr(
    const float* __restrict__ geo, const float* __restrict__ app, const float* __restrict__ con,
    float* __restrict__ out,
    const float* __restrict__ W2c, const float* __restrict__ b2c,
    const float* __restrict__ W2r, const float* __restrict__ b2r,
    const float* __restrict__ W2l, const float* __restrict__ b2l)
{
    __shared__ float sP[32 * 132];
    __shared__ float sQ[32 * 128];
    __shared__ float sW[128];
    const int g = blockIdx.x;
    const int tid = threadIdx.x;

    if (g < LG_BLOCKS) {
        const int t = g / 50;
        const int r50 = g % 50;
        const int b = r50 / 25;
        const int r25 = r50 % 25;
        const int i0 = (r25 / 5) * 32;
        const int j0 = (r25 % 5) * 32;
        const float* W2 = (t==0 ? W2c : (t==1 ? W2r : W2l));
        const float* b2 = (t==0 ? b2c : (t==1 ? b2r : b2l));
        const size_t boff = (size_t)b * NN * FF;
        const float* Pb = g_PQ + (size_t)(t*2 + 0) * MM * FF + boff;
        const float* Qb = g_PQ + (size_t)(t*2 + 1) * MM * FF + boff;
        const int il = tid >> 5, jl = tid & 31;
        const int lr = tid >> 3, lv = tid & 7;

        float acc[4] = {0.f, 0.f, 0.f, 0.f};
        for (int fc = 0; fc < 4; fc++) {
            const int f0 = fc * 128;
            {
                const size_t ro = (size_t)(j0 + lr) * FF + f0;
                float* dp = sP + lr * 132;
                #pragma unroll
                for (int u = 0; u < 4; u++) {
                    const int fl = (lv + u * 8) * 4;
                    *(float4*)(dp + fl) = *(const float4*)(Pb + ro + fl);
                }
            }
            {
                const size_t ro = (size_t)(i0 + lr) * FF + f0;
                float* dp = sQ + lr * 128;
                #pragma unroll
                for (int u = 0; u < 4; u++) {
                    const int fl = (lv + u * 8) * 4;
                    *(float4*)(dp + fl) = *(const float4*)(Qb + ro + fl);
                }
            }
            if (tid < 128) {
                const float2 w2v = ((const float2*)W2)[f0 + tid];
                sW[tid] = w2v.x - w2v.y;
            }
            __syncthreads();

            const float* pr = sP + jl * 132;
            const float* q0 = sQ + (il * 4) * 128;
            #pragma unroll 4
            for (int f = 0; f < 128; f += 4) {
                const float4 p = *(const float4*)(pr + f);
                const float4 w = *(const float4*)(sW + f);
                #pragma unroll
                for (int a = 0; a < 4; a++) {
                    const float4 q = *(const float4*)(q0 + a * 128 + f);
                    acc[a] = fmaf(fmaxf(p.x + q.x, 0.f), w.x, acc[a]);
                    acc[a] = fmaf(fmaxf(p.y + q.y, 0.f), w.y, acc[a]);
                    acc[a] = fmaf(fmaxf(p.z + q.z, 0.f), w.z, acc[a]);
                    acc[a] = fmaf(fmaxf(p.w + q.w, 0.f), w.w, acc[a]);
                }
            }
            __syncthreads();
        }

        const float bd = b2[0] - b2[1];
        float2* o = (float2*)(out + (size_t)t * LOGIT_ELEMS) + (size_t)b * NP;
        const int j = j0 + jl;
        #pragma unroll
        for (int a = 0; a < 4; a++) {
            const float d = acc[a] + bd;
            const float p0 = 1.0f / (1.0f + __expf(-d));
            o[(size_t)(i0 + il*4 + a) * NN + j] = make_float2(p0, 1.0f - p0);
        }
    } else {
        writer_role(WR_SPLIT + (g - LG_BLOCKS), geo, app, con, out, tid);
    }
}

extern "C" void kernel_launch(void* const* d_in, const int* in_sizes, int n_in,
                              void* d_out, int out_size) {
    const float* geo = (const float*)d_in[0];
    const float* app = (const float*)d_in[1];
    const float* con = (const float*)d_in[2];
    const float* W1c = (const float*)d_in[3];
    const float* b1c = (const float*)d_in[4];
    const float* W2c = (const float*)d_in[5];
    const float* b2c = (const float*)d_in[6];
    const float* W1r = (const float*)d_in[7];
    const float* b1r = (const float*)d_in[8];
    const float* W2r = (const float*)d_in[9];
    const float* b2r = (const float*)d_in[10];
    const float* W1l = (const float*)d_in[11];
    const float* b1l = (const float*)d_in[12];
    const float* W2l = (const float*)d_in[13];
    const float* b2l = (const float*)d_in[14];
    float* out = (float*)d_out;

    k1_gemm_wr<<<GEMM_BLOCKS + WRA_BLOCKS, 256>>>(geo, app, con,
                                                  W1c, b1c, W1r, b1r, W1l, b1l, out);
    k2_lg_wr<<<LG_BLOCKS + WRB_BLOCKS, 256>>>(geo, app, con, out,
                                              W2c, b2c, W2r, b2r, W2l, b2l);
}

// round 9
// speedup vs baseline: 1.2390x; 1.0549x over previous
#include <cuda_runtime.h>
#include <math.h>
#include <stdint.h>

#define BB 2
#define NN 160
#define HH 256
#define C3 768
#define FF 512
#define NP (NN*NN)            // 25600
#define MM (BB*NN)            // 320
#define LOGIT_ELEMS (BB*NP*2) // 102400 per head
#define EMB_OFF (3*LOGIT_ELEMS)

// PQ scratch: [h = t*2+s][m][f]
__device__ float g_PQ[3 * 2 * MM * FF];

#define FFMA2(acc, a, b) asm("fma.rn.f32x2 %0, %1, %2, %0;" : "+l"(acc) : "l"(a), "l"(b))
#define PACKDUP(d, x)    asm("mov.b64 %0, {%1, %1};" : "=l"(d) : "r"(__float_as_uint(x)))
#define UNPK(lo, hi, v)  asm("mov.b64 {%0, %1}, %2;" : "=r"(lo), "=r"(hi) : "l"(v))

#define BM 64
#define BN 64
#define BK 16
#define NK 48
#define AST 68
#define GEMM_BLOCKS 240
#define JT 10                        // j's per writer tile
#define WR_TILES (BB*NN*(NN/JT))     // 5120
#define WRA_BLOCKS 2560
#define WRB_BLOCKS 2560
#define LG_BLOCKS 150

// shared memory union (bytes):
//  gemm:   As 2*16*68*4 = 8704 | Bs 2*16*64*4 = 8192  -> 16896
//  logits: sP 16896 | sQ 16384 | sW 512               -> 33792
//  writer: 11 rows * 3072B + mbar 8                   -> 33800
#define SMEM_BYTES 33824

// ---------------- writer role: TMA bulk pipeline ----------------
// wb in [0, 5120): b = wb/2560, i = (wb%2560)/16, j0 = ((wb%2560)%16)*10
__device__ __forceinline__ void writer_role(
    int wb,
    const float* __restrict__ geo, const float* __restrict__ app, const float* __restrict__ con,
    float* __restrict__ out, int tid, char* sm)
{
    const int b  = wb / 2560;
    const int rem = wb % 2560;
    const int i  = rem / 16;
    const int j0 = (rem % 16) * JT;

    const uint32_t sbase = (uint32_t)__cvta_generic_to_shared(sm);
    const uint32_t mbar  = sbase + 11 * 3072;

    if (tid == 0) {
        asm volatile("mbarrier.init.shared.b64 [%0], 1;" :: "r"(mbar) : "memory");
    }
    __syncthreads();
    if (tid == 0) {
        asm volatile("mbarrier.arrive.expect_tx.shared.b64 _, [%0], %1;"
                     :: "r"(mbar), "r"(11u * 3072u) : "memory");
    }
    __syncthreads();

    // 33 bulk loads: rows 0..9 = emb[j0+r], row 10 = emb[i]; 3 segments each
    if (tid < 33) {
        const int r = tid / 3, seg = tid - 3 * (tid / 3);
        const int n = (r < JT) ? (j0 + r) : i;
        const float* src = ((seg == 0) ? geo : (seg == 1) ? app : con)
                           + ((size_t)b * NN + n) * HH;
        asm volatile(
            "cp.async.bulk.shared::cluster.global.mbarrier::complete_tx::bytes "
            "[%0], [%1], %2, [%3];"
            :: "r"(sbase + (uint32_t)(r * 3072 + seg * 1024)), "l"(src),
               "r"(1024u), "r"(mbar) : "memory");
    }

    // 20 bulk stores: pair (i, j0+jj) -> [emb[j] | emb[i]] (2 x 3072B)
    if (tid < 2 * JT) {
        // wait for loads (phase 0)
        asm volatile(
            "{\n\t.reg .pred P;\n"
            "W%=:\n\t"
            "mbarrier.try_wait.parity.shared.b64 P, [%0], 0, 0x989680;\n\t"
            "@!P bra W%=;\n\t}"
            :: "r"(mbar) : "memory");

        const int jj = tid >> 1, half = tid & 1;
        const size_t pidx = (size_t)b * NP + (size_t)i * NN + (j0 + jj);
        float* dst = out + EMB_OFF + pidx * 1536 + half * 768;
        const uint32_t src = sbase + (uint32_t)((half ? JT : jj) * 3072);
        asm volatile(
            "cp.async.bulk.global.shared::cta.bulk_group [%0], [%1], %2;"
            :: "l"(dst), "r"(src), "r"(3072u) : "memory");
        asm volatile("cp.async.bulk.commit_group;" ::: "memory");
        asm volatile("cp.async.bulk.wait_group 0;" ::: "memory");
    }
    __syncthreads();
}

// ---------------- Kernel 1: full-K GEMM + writer half A ----------------
__global__ __launch_bounds__(256) void k1_gemm_wr(
    const float* __restrict__ geo, const float* __restrict__ app, const float* __restrict__ con,
    const float* __restrict__ W1c, const float* __restrict__ b1c,
    const float* __restrict__ W1r, const float* __restrict__ b1r,
    const float* __restrict__ W1l, const float* __restrict__ b1l,
    float* __restrict__ out)
{
    __shared__ __align__(128) char sm[SMEM_BYTES];
    const int g = blockIdx.x;
    const int tid = threadIdx.x;

    if (g < GEMM_BLOCKS) {
        float (*As)[BK*AST] = (float(*)[BK*AST])sm;
        float (*Bs)[BK*BN]  = (float(*)[BK*BN])(sm + 2*BK*AST*4);
        const int nt = g % 48;
        const int mt = g / 48;
        const int t  = nt >> 4;
        const int s  = (nt >> 3) & 1;
        const int f0 = (nt & 7) * BN;
        const float* W1 = (t==0 ? W1c : (t==1 ? W1r : W1l)) + (size_t)s * C3 * FF;
        const float* b1 = (t==0 ? b1c : (t==1 ? b1r : b1l));
        const int m0 = mt * BM;

        const int arow = tid >> 2, av = tid & 3;
        const int kr = tid >> 4, fo = (tid & 15) * 4;
        const int rg = tid >> 4, cg = tid & 15;

        unsigned long long acc2[4][2];
        #pragma unroll
        for (int a = 0; a < 4; a++) { acc2[a][0] = 0ull; acc2[a][1] = 0ull; }

        float4 pa, pb;
        pa = *(const float4*)(geo + (size_t)(m0 + arow) * HH + av * 4);
        pb = *(const float4*)(W1 + (size_t)kr * FF + f0 + fo);
        As[0][(av*4+0)*AST + arow] = pa.x;
        As[0][(av*4+1)*AST + arow] = pa.y;
        As[0][(av*4+2)*AST + arow] = pa.z;
        As[0][(av*4+3)*AST + arow] = pa.w;
        *(float4*)&Bs[0][kr*BN + fo] = pb;
        __syncthreads();

        for (int kt = 0; kt < NK; kt++) {
            const int cur = kt & 1;
            const int nxt = cur ^ 1;
            if (kt + 1 < NK) {
                const int c0 = (kt + 1) * BK;
                const float* segp = (c0 < 256) ? geo : ((c0 < 512) ? app : con);
                pa = *(const float4*)(segp + (size_t)(m0 + arow) * HH + (c0 & 255) + av * 4);
                pb = *(const float4*)(W1 + (size_t)(c0 + kr) * FF + f0 + fo);
            }
            #pragma unroll
            for (int k = 0; k < BK; k++) {
                const float4 a4 = *(const float4*)&As[cur][k*AST + rg*4];
                const ulonglong2 b2v = *(const ulonglong2*)&Bs[cur][k*BN + cg*4];
                float avv[4] = {a4.x, a4.y, a4.z, a4.w};
                #pragma unroll
                for (int a = 0; a < 4; a++) {
                    unsigned long long ad;
                    PACKDUP(ad, avv[a]);
                    FFMA2(acc2[a][0], ad, b2v.x);
                    FFMA2(acc2[a][1], ad, b2v.y);
                }
            }
            if (kt + 1 < NK) {
                __syncthreads();
                As[nxt][(av*4+0)*AST + arow] = pa.x;
                As[nxt][(av*4+1)*AST + arow] = pa.y;
                As[nxt][(av*4+2)*AST + arow] = pa.z;
                As[nxt][(av*4+3)*AST + arow] = pa.w;
                *(float4*)&Bs[nxt][kr*BN + fo] = pb;
                __syncthreads();
            }
        }

        const bool addb = (s == 1);
        float bv[4] = {0.f, 0.f, 0.f, 0.f};
        if (addb) {
            const float4 tb = *(const float4*)(b1 + f0 + cg*4);
            bv[0]=tb.x; bv[1]=tb.y; bv[2]=tb.z; bv[3]=tb.w;
        }
        const size_t hb = (size_t)(t*2 + s) * MM * FF;
        #pragma unroll
        for (int a = 0; a < 4; a++) {
            const int m = m0 + rg*4 + a;
            unsigned int lo0, hi0, lo1, hi1;
            UNPK(lo0, hi0, acc2[a][0]);
            UNPK(lo1, hi1, acc2[a][1]);
            *(float4*)(g_PQ + hb + (size_t)m * FF + f0 + cg*4) =
                make_float4(__uint_as_float(lo0) + bv[0], __uint_as_float(hi0) + bv[1],
                            __uint_as_float(lo1) + bv[2], __uint_as_float(hi1) + bv[3]);
        }
    } else {
        writer_role(g - GEMM_BLOCKS, geo, app, con, out, tid, sm);
    }
}

// ---------------- Kernel 2: logits (32i x 32j, acc[4]) + writer half B ----------------
__global__ __launch_bounds__(256) void k2_lg_wr(
    const float* __restrict__ geo, const float* __restrict__ app, const float* __restrict__ con,
    float* __restrict__ out,
    const float* __restrict__ W2c, const float* __restrict__ b2c,
    const float* __restrict__ W2r, const float* __restrict__ b2r,
    const float* __restrict__ W2l, const float* __restrict__ b2l)
{
    __shared__ __align__(128) char sm[SMEM_BYTES];
    const int g = blockIdx.x;
    const int tid = threadIdx.x;

    if (g < LG_BLOCKS) {
        float* sP = (float*)sm;            // 32*132
        float* sQ = sP + 32*132;           // 32*128
        float* sW = sQ + 32*128;           // 128
        const int t = g / 50;
        const int r50 = g % 50;
        const int b = r50 / 25;
        const int r25 = r50 % 25;
        const int i0 = (r25 / 5) * 32;
        const int j0 = (r25 % 5) * 32;
        const float* W2 = (t==0 ? W2c : (t==1 ? W2r : W2l));
        const float* b2 = (t==0 ? b2c : (t==1 ? b2r : b2l));
        const size_t boff = (size_t)b * NN * FF;
        const float* Pb = g_PQ + (size_t)(t*2 + 0) * MM * FF + boff;
        const float* Qb = g_PQ + (size_t)(t*2 + 1) * MM * FF + boff;
        const int il = tid >> 5, jl = tid & 31;
        const int lr = tid >> 3, lv = tid & 7;

        float acc[4] = {0.f, 0.f, 0.f, 0.f};
        for (int fc = 0; fc < 4; fc++) {
            const int f0 = fc * 128;
            {
                const size_t ro = (size_t)(j0 + lr) * FF + f0;
                float* dp = sP + lr * 132;
                #pragma unroll
                for (int u = 0; u < 4; u++) {
                    const int fl = (lv + u * 8) * 4;
                    *(float4*)(dp + fl) = *(const float4*)(Pb + ro + fl);
                }
            }
            {
                const size_t ro = (size_t)(i0 + lr) * FF + f0;
                float* dp = sQ + lr * 128;
                #pragma unroll
                for (int u = 0; u < 4; u++) {
                    const int fl = (lv + u * 8) * 4;
                    *(float4*)(dp + fl) = *(const float4*)(Qb + ro + fl);
                }
            }
            if (tid < 128) {
                const float2 w2v = ((const float2*)W2)[f0 + tid];
                sW[tid] = w2v.x - w2v.y;
            }
            __syncthreads();

            const float* pr = sP + jl * 132;
            const float* q0 = sQ + (il * 4) * 128;
            #pragma unroll 4
            for (int f = 0; f < 128; f += 4) {
                const float4 p = *(const float4*)(pr + f);
                const float4 w = *(const float4*)(sW + f);
                #pragma unroll
                for (int a = 0; a < 4; a++) {
                    const float4 q = *(const float4*)(q0 + a * 128 + f);
                    acc[a] = fmaf(fmaxf(p.x + q.x, 0.f), w.x, acc[a]);
                    acc[a] = fmaf(fmaxf(p.y + q.y, 0.f), w.y, acc[a]);
                    acc[a] = fmaf(fmaxf(p.z + q.z, 0.f), w.z, acc[a]);
                    acc[a] = fmaf(fmaxf(p.w + q.w, 0.f), w.w, acc[a]);
                }
            }
            __syncthreads();
        }

        const float bd = b2[0] - b2[1];
        float2* o = (float2*)(out + (size_t)t * LOGIT_ELEMS) + (size_t)b * NP;
        const int j = j0 + jl;
        #pragma unroll
        for (int a = 0; a < 4; a++) {
            const float d = acc[a] + bd;
            const float p0 = 1.0f / (1.0f + __expf(-d));
            o[(size_t)(i0 + il*4 + a) * NN + j] = make_float2(p0, 1.0f - p0);
        }
    } else {
        writer_role(WRA_BLOCKS + (g - LG_BLOCKS), geo, app, con, out, tid, sm);
    }
}

extern "C" void kernel_launch(void* const* d_in, const int* in_sizes, int n_in,
                              void* d_out, int out_size) {
    const float* geo = (const float*)d_in[0];
    const float* app = (const float*)d_in[1];
    const float* con = (const float*)d_in[2];
    const float* W1c = (const float*)d_in[3];
    const float* b1c = (const float*)d_in[4];
    const float* W2c = (const float*)d_in[5];
    const float* b2c = (const float*)d_in[6];
    const float* W1r = (const float*)d_in[7];
    const float* b1r = (const float*)d_in[8];
    const float* W2r = (const float*)d_in[9];
    const float* b2r = (const float*)d_in[10];
    const float* W1l = (const float*)d_in[11];
    const float* b1l = (const float*)d_in[12];
    const float* W2l = (const float*)d_in[13];
    const float* b2l = (const float*)d_in[14];
    float* out = (float*)d_out;

    k1_gemm_wr<<<GEMM_BLOCKS + WRA_BLOCKS, 256>>>(geo, app, con,
                                                  W1c, b1c, W1r, b1r, W1l, b1l, out);
    k2_lg_wr<<<LG_BLOCKS + WRB_BLOCKS, 256>>>(geo, app, con, out,
                                              W2c, b2c, W2r, b2r, W2l, b2l);
}